// round 12
// baseline (speedup 1.0000x reference)
#include <cuda_runtime.h>
#include <cuda_fp16.h>

// Flow attention, N=4, L=S=16384, H=8, D=16, fp32, layout [N, L, H, D].
#define NB 4
#define LL 16384
#define HH 8
#define DD 16
#define HD 128          // H*D floats per (n,l) row
#define NHTOT 32
#define EPSF 1e-6f
#define LN_EPSF 1e-5f

#define CH1 256
#define ROWS1 (LL / CH1)      // 64
#define CH2 256
#define ROWS2 (LL / CH2)      // 64
#define CH4 64
#define ROWS4 (LL / CH4)      // 256
#define TILES4 (ROWS4 / 32)   // 8
#define CH5 256
#define ROWS5 (LL / CH5)      // 64

// ---- scratch (device globals: allowed) ----
__device__ __half g_qs[(size_t)NB * LL * HD];   // sigm(Q), fp16
__device__ __half g_ks[(size_t)NB * LL * HD];   // sigm(K), fp16
__device__ float g_p_qsum[NB][CH1][HD];
__device__ float g_p_ksum[NB][CH1][HD];
__device__ float g_qsum[NB][HD];
__device__ float g_ksum[NB][HD];
__device__ float g_p_qn[NB][CH2][HD];
__device__ float g_p_kn[NB][CH2][HD];
__device__ float g_qn[NB][HD];
__device__ float g_kn[NB][HD];
__device__ float g_p_s[NHTOT][CH4];        // per-chunk sum exp(cr)
__device__ float g_p_kv[NHTOT][CH4][256];  // unnormalized kv partials
__device__ float g_kv[NHTOT][256];

// sigmoid via MUFU.TANH: sigm(x) = 0.5*tanh(x/2)+0.5  (1 MUFU)
__device__ __forceinline__ float sigm(float x) {
    float t;
    asm("tanh.approx.f32 %0, %1;" : "=f"(t) : "f"(x * 0.5f));
    return fmaf(0.5f, t, 0.5f);
}
// 8-lane segment sum via shuffle butterfly; all lanes get the result
__device__ __forceinline__ float red8(float v) {
    v += __shfl_xor_sync(0xffffffffu, v, 4, 8);
    v += __shfl_xor_sync(0xffffffffu, v, 2, 8);
    v += __shfl_xor_sync(0xffffffffu, v, 1, 8);
    return v;
}
__device__ __forceinline__ float red32(float v) {
    v += __shfl_xor_sync(0xffffffffu, v, 16);
    v += __shfl_xor_sync(0xffffffffu, v, 8);
    v += __shfl_xor_sync(0xffffffffu, v, 4);
    v += __shfl_xor_sync(0xffffffffu, v, 2);
    v += __shfl_xor_sync(0xffffffffu, v, 1);
    return v;
}
// packed f32x2 helpers (sm_100+ PTX)
__device__ __forceinline__ unsigned long long pk2(float a, float b) {
    unsigned long long r;
    asm("mov.b64 %0, {%1, %2};" : "=l"(r)
        : "r"(__float_as_uint(a)), "r"(__float_as_uint(b)));
    return r;
}
__device__ __forceinline__ float2 upk2(unsigned long long v) {
    unsigned lo, hi;
    asm("mov.b64 {%0, %1}, %2;" : "=r"(lo), "=r"(hi) : "l"(v));
    return make_float2(__uint_as_float(lo), __uint_as_float(hi));
}
__device__ __forceinline__ unsigned long long fma2(unsigned long long a,
                                                  unsigned long long b,
                                                  unsigned long long c) {
    unsigned long long r;
    asm("fma.rn.f32x2 %0, %1, %2, %3;" : "=l"(r) : "l"(a), "l"(b), "l"(c));
    return r;
}

// ---------- Pass 1: sigmoid + fp16 scratch + per-chunk sums ----------
__global__ __launch_bounds__(128) void k_sums(const float* __restrict__ Q,
                                              const float* __restrict__ K) {
    int c = blockIdx.x, n = blockIdx.y, t = threadIdx.x;
    size_t base = ((size_t)n * LL + (size_t)c * ROWS1) * HD + t;
    float sq = 0.f, sk = 0.f;
#pragma unroll 4
    for (int i = 0; i < ROWS1; i++) {
        size_t off = base + (size_t)i * HD;
        float qs = sigm(Q[off]);
        float ks = sigm(K[off]);
        g_qs[off] = __float2half_rn(qs);
        g_ks[off] = __float2half_rn(ks);
        sq += qs; sk += ks;
    }
    g_p_qsum[n][c][t] = sq;
    g_p_ksum[n][c][t] = sk;
}

// fixup, grid=32: b -> a=b&1, n=(b>>1)&3, tq=b>>3; block 1024 = 32t x 32s
__global__ __launch_bounds__(1024) void r_sums2() {
    __shared__ float red[32][33];
    int b = blockIdx.x;
    int a = b & 1, n = (b >> 1) & 3, tq = b >> 3;
    int lane = threadIdx.x & 31;
    int s = threadIdx.x >> 5;
    int t = tq * 32 + lane;
    float acc = 0.f;
#pragma unroll
    for (int j = 0; j < CH1 / 32; j++) {
        int c = s * (CH1 / 32) + j;
        acc += a ? g_p_ksum[n][c][t] : g_p_qsum[n][c][t];
    }
    red[s][lane] = acc;
    __syncthreads();
    if (threadIdx.x < 32) {
        float r = 0.f;
#pragma unroll
        for (int j = 0; j < 32; j++) r += red[j][threadIdx.x];
        int tt = tq * 32 + (int)threadIdx.x;
        if (a) g_ksum[n][tt] = r; else g_qsum[n][tt] = r;
    }
}

// ---------- Pass 2: qn = sum q*nr, kn = sum k*nc (fp16 reads) ----------
__global__ __launch_bounds__(256) void k_norm() {
    __shared__ float smq[8][HD];
    __shared__ float smk[8][HD];
    int c = blockIdx.x, n = blockIdx.y;
    int t = threadIdx.x, w = t >> 5, lane = t & 31;
    int g = lane >> 3, dp = lane & 7;
    int ta = g * 16 + 2 * dp, tb = (g + 4) * 16 + 2 * dp;
    float2 kseA = {g_ksum[n][ta] + EPSF, g_ksum[n][ta + 1] + EPSF};
    float2 kseB = {g_ksum[n][tb] + EPSF, g_ksum[n][tb + 1] + EPSF};
    float2 qseA = {g_qsum[n][ta] + EPSF, g_qsum[n][ta + 1] + EPSF};
    float2 qseB = {g_qsum[n][tb] + EPSF, g_qsum[n][tb + 1] + EPSF};
    float CkA = red8(kseA.x + kseA.y) * EPSF;
    float CkB = red8(kseB.x + kseB.y) * EPSF;
    float CqA = red8(qseA.x + qseA.y) * EPSF;
    float CqB = red8(qseB.x + qseB.y) * EPSF;
    float2 aqA = {0.f, 0.f}, aqB = {0.f, 0.f};
    float2 akA = {0.f, 0.f}, akB = {0.f, 0.f};
    size_t rb0 = ((size_t)n * LL + (size_t)c * ROWS2) * HD;
#pragma unroll 2
    for (int i = 0; i < ROWS2 / 8; i++) {
        size_t rb = rb0 + (size_t)(w + 8 * i) * HD;
        float2 qa = __half22float2(*(const __half2*)(g_qs + rb + ta));
        float2 qb = __half22float2(*(const __half2*)(g_qs + rb + tb));
        float2 ka = __half22float2(*(const __half2*)(g_ks + rb + ta));
        float2 kb = __half22float2(*(const __half2*)(g_ks + rb + tb));
        float d1A = red8(fmaf(qa.y, kseA.y, qa.x * kseA.x)) + CkA;
        float d1B = red8(fmaf(qb.y, kseB.y, qb.x * kseB.x)) + CkB;
        float d2A = red8(fmaf(ka.y, qseA.y, ka.x * qseA.x)) + CqA;
        float d2B = red8(fmaf(kb.y, qseB.y, kb.x * qseB.x)) + CqB;
        float nrA = __fdividef(1.f, d1A), nrB = __fdividef(1.f, d1B);
        float ncA = __fdividef(1.f, d2A), ncB = __fdividef(1.f, d2B);
        aqA.x = fmaf(qa.x, nrA, aqA.x); aqA.y = fmaf(qa.y, nrA, aqA.y);
        aqB.x = fmaf(qb.x, nrB, aqB.x); aqB.y = fmaf(qb.y, nrB, aqB.y);
        akA.x = fmaf(ka.x, ncA, akA.x); akA.y = fmaf(ka.y, ncA, akA.y);
        akB.x = fmaf(kb.x, ncB, akB.x); akB.y = fmaf(kb.y, ncB, akB.y);
    }
    *(float2*)&smq[w][ta] = aqA; *(float2*)&smq[w][tb] = aqB;
    *(float2*)&smk[w][ta] = akA; *(float2*)&smk[w][tb] = akB;
    __syncthreads();
    if (t < 128) {
        float s = 0.f;
#pragma unroll
        for (int w2 = 0; w2 < 8; w2++) s += smq[w2][t];
        g_p_qn[n][c][t] = s;
    } else {
        int t2 = t - 128;
        float s = 0.f;
#pragma unroll
        for (int w2 = 0; w2 < 8; w2++) s += smk[w2][t2];
        g_p_kn[n][c][t2] = s;
    }
}

__global__ __launch_bounds__(1024) void r_norm2() {
    __shared__ float red[32][33];
    int b = blockIdx.x;
    int a = b & 1, n = (b >> 1) & 3, tq = b >> 3;
    int lane = threadIdx.x & 31;
    int s = threadIdx.x >> 5;
    int t = tq * 32 + lane;
    float acc = 0.f;
#pragma unroll
    for (int j = 0; j < CH2 / 32; j++) {
        int c = s * (CH2 / 32) + j;
        acc += a ? g_p_kn[n][c][t] : g_p_qn[n][c][t];
    }
    red[s][lane] = acc;
    __syncthreads();
    if (threadIdx.x < 32) {
        float r = 0.f;
#pragma unroll
        for (int j = 0; j < 32; j++) r += red[j][threadIdx.x];
        int tt = tq * 32 + (int)threadIdx.x;
        if (a) g_kn[n][tt] = r; else g_qn[n][tt] = r;
    }
}

// ---------- Pass 3: kv accumulation, shift-free softmax weights ----------
__global__ __launch_bounds__(256) void k_kv(const float* __restrict__ V) {
    __shared__ __align__(16) float k_sh[2][32][16];
    __shared__ __align__(16) float v_sh[2][32][16];
    __shared__ float w_sh[2][32];
    __shared__ float s_sh[32];
    __shared__ float red_sh[8][16][16];
    int c = blockIdx.x, h = blockIdx.y, n = blockIdx.z;
    int t = threadIdx.x;  // 256
    int nh = n * HH + h;
    int lrow = t >> 3, ldp = t & 7;
    float2 qne = {g_qn[n][h * 16 + 2 * ldp] + EPSF,
                  g_qn[n][h * 16 + 2 * ldp + 1] + EPSF};
    float Ccr = red8(qne.x + qne.y) * EPSF;
    int pos = t & 15, sl = t >> 4;
    int d4 = (pos & 3) * 4, e4 = (pos >> 2) * 4;
    float acc[16];
#pragma unroll
    for (int i = 0; i < 16; i++) acc[i] = 0.f;
    float s_acc = 0.f;   // valid on ldp==0 threads
    size_t base = ((size_t)n * LL + (size_t)c * ROWS4) * HD + h * DD;
    // prologue: load tile 0 into buffer 0
    {
        size_t off = base + (size_t)lrow * HD + 2 * ldp;
        float2 kf = __half22float2(*(const __half2*)(g_ks + off));
        float2 vf = *(const float2*)(V + off);
        *(float2*)&k_sh[0][lrow][2 * ldp] = kf;
        *(float2*)&v_sh[0][lrow][2 * ldp] = vf;
        float cr = red8(fmaf(kf.y, qne.y, kf.x * qne.x)) + Ccr;
        if (ldp == 0) { float w = __expf(cr); w_sh[0][lrow] = w; s_acc += w; }
    }
    for (int tile = 0; tile < TILES4; tile++) {
        int p = tile & 1;
        __syncthreads();   // buffer p fully written; buffer 1-p free
        if (tile + 1 < TILES4) {
            size_t off = base + (size_t)((tile + 1) * 32 + lrow) * HD + 2 * ldp;
            float2 kf = __half22float2(*(const __half2*)(g_ks + off));
            float2 vf = *(const float2*)(V + off);
            *(float2*)&k_sh[1 - p][lrow][2 * ldp] = kf;
            *(float2*)&v_sh[1 - p][lrow][2 * ldp] = vf;
            float cr = red8(fmaf(kf.y, qne.y, kf.x * qne.x)) + Ccr;
            if (ldp == 0) { float w = __expf(cr); w_sh[1 - p][lrow] = w; s_acc += w; }
        }
        // 4x4 register-tiled rank-1 accumulation from buffer p
#pragma unroll
        for (int j = 0; j < 2; j++) {
            int ss = sl + j * 16;
            float c0 = w_sh[p][ss];
            float4 kq = *reinterpret_cast<const float4*>(&k_sh[p][ss][d4]);
            float4 vq = *reinterpret_cast<const float4*>(&v_sh[p][ss][e4]);
            float ka[4] = {kq.x * c0, kq.y * c0, kq.z * c0, kq.w * c0};
            float va[4] = {vq.x, vq.y, vq.z, vq.w};
#pragma unroll
            for (int di = 0; di < 4; di++)
#pragma unroll
                for (int ei = 0; ei < 4; ei++)
                    acc[di * 4 + ei] = fmaf(ka[di], va[ei], acc[di * 4 + ei]);
        }
    }
    if (ldp == 0) s_sh[lrow] = s_acc;
#pragma unroll
    for (int i = 0; i < 16; i++) acc[i] += __shfl_xor_sync(0xffffffffu, acc[i], 16);
    int w = t >> 5, lane = t & 31;
    __syncthreads();
    if (t < 32) {
        float z = red32(s_sh[t]);
        if (t == 0) g_p_s[nh][c] = z;
    }
    if (lane < 16) {
#pragma unroll
        for (int i = 0; i < 16; i++) red_sh[w][lane][i] = acc[i];
    }
    __syncthreads();
    {
        int posp = t >> 4, ip = t & 15;
        float s = 0.f;
#pragma unroll
        for (int w2 = 0; w2 < 8; w2++) s += red_sh[w2][posp][ip];
        int dd4 = (posp & 3) * 4, ee4 = (posp >> 2) * 4;
        int di = ip >> 2, ei = ip & 3;
        g_p_kv[nh][c][(dd4 + di) * 16 + (ee4 + ei)] = s;
    }
}

// combine chunk kv partials, normalize by Z, fold in S factor
__global__ __launch_bounds__(256) void r_kv() {
    __shared__ float sf[CH4];
    __shared__ float scale_sh;
    int nh = blockIdx.x, t = threadIdx.x;
    if (t < CH4) sf[t] = g_p_s[nh][t];
    __syncthreads();
    if (t == 0) {
        float Z = 0.f;
        for (int c = 0; c < CH4; c++) Z += sf[c];
        scale_sh = (float)LL / Z;
    }
    __syncthreads();
    float scale = scale_sh;
    float s = 0.f;
#pragma unroll 8
    for (int c = 0; c < CH4; c++) s += g_p_kv[nh][c][t];
    g_kv[nh][t] = s * scale;
}

// ---------- Pass 5: out = LN(v + (q @ kv) * nr * rr) ----------
__global__ __launch_bounds__(128) void k_out(const float* __restrict__ V,
                                             const float* __restrict__ G,
                                             const float* __restrict__ B,
                                             float* __restrict__ O) {
    int c = blockIdx.x, n = blockIdx.y, t = threadIdx.x;  // 128
    int rh = t >> 6;          // which of 2 rows per iter
    int h = (t >> 3) & 7;
    int ep = t & 7;           // e = 2ep, 2ep+1
    int nh = n * HH + h;
    int tb = h * 16 + 2 * ep;
    // full head vectors of ksum+eps and kn+eps, packed as f32x2
    unsigned long long ksep[8], knep[8];
    float Ck = 0.f, Cn = 0.f;
#pragma unroll
    for (int i = 0; i < 8; i++) {
        float a0 = g_ksum[n][h * 16 + 2 * i] + EPSF;
        float a1 = g_ksum[n][h * 16 + 2 * i + 1] + EPSF;
        float b0 = g_kn[n][h * 16 + 2 * i] + EPSF;
        float b1 = g_kn[n][h * 16 + 2 * i + 1] + EPSF;
        ksep[i] = pk2(a0, a1); knep[i] = pk2(b0, b1);
        Ck += a0 + a1; Cn += b0 + b1;
    }
    Ck *= EPSF; Cn *= EPSF;
    float2 gam = {G[2 * ep], G[2 * ep + 1]};
    float2 bet = {B[2 * ep], B[2 * ep + 1]};
    unsigned long long kvp[16];
#pragma unroll
    for (int d = 0; d < 16; d++)
        kvp[d] = pk2(g_kv[nh][d * 16 + 2 * ep], g_kv[nh][d * 16 + 2 * ep + 1]);
    for (int i = 0; i < ROWS5 / 2; i++) {
        int l = c * ROWS5 + 2 * i + rh;
        size_t rowb = ((size_t)n * LL + (size_t)l) * HD;
        const __half* qh = g_qs + rowb + h * 16;
        uint4 a0 = *(const uint4*)qh;
        uint4 a1 = *(const uint4*)(qh + 8);
        float2 qp[8];
        qp[0] = __half22float2(*(const __half2*)&a0.x);
        qp[1] = __half22float2(*(const __half2*)&a0.y);
        qp[2] = __half22float2(*(const __half2*)&a0.z);
        qp[3] = __half22float2(*(const __half2*)&a0.w);
        qp[4] = __half22float2(*(const __half2*)&a1.x);
        qp[5] = __half22float2(*(const __half2*)&a1.y);
        qp[6] = __half22float2(*(const __half2*)&a1.z);
        qp[7] = __half22float2(*(const __half2*)&a1.w);
        // x pair: sum_d q[d] * kv[d][e-pair] via packed fma (scalar-dup packs)
        unsigned long long acc = pk2(0.f, 0.f);
#pragma unroll
        for (int j = 0; j < 8; j++) {
            acc = fma2(pk2(qp[j].x, qp[j].x), kvp[2 * j], acc);
            acc = fma2(pk2(qp[j].y, qp[j].y), kvp[2 * j + 1], acc);
        }
        float2 x = upk2(acc);
        // d1, d2: full-row dots in registers (no cross-lane traffic)
        unsigned long long accd1 = pk2(0.f, 0.f), accd2 = pk2(0.f, 0.f);
#pragma unroll
        for (int j = 0; j < 8; j++) {
            unsigned long long qj = pk2(qp[j].x, qp[j].y);
            accd1 = fma2(qj, ksep[j], accd1);
            accd2 = fma2(qj, knep[j], accd2);
        }
        float2 d1p = upk2(accd1), d2p = upk2(accd2);
        float d1 = d1p.x + d1p.y + Ck;
        float d2 = d2p.x + d2p.y + Cn;
        float s = __fdividef(1.f, d1) * sigm(d2);
        float2 v2 = *(const float2*)(V + rowb + tb);
        float y0 = fmaf(x.x, s, v2.x);
        float y1 = fmaf(x.y, s, v2.y);
        float mean = red8(y0 + y1) * 0.0625f;
        float ym0 = y0 - mean, ym1 = y1 - mean;
        float var = red8(fmaf(ym1, ym1, ym0 * ym0)) * 0.0625f;
        float rs = rsqrtf(var + LN_EPSF);
        float2 o;
        o.x = fmaf(ym0 * rs, gam.x, bet.x);
        o.y = fmaf(ym1 * rs, gam.y, bet.y);
        *(float2*)(O + rowb + tb) = o;
    }
}

extern "C" void kernel_launch(void* const* d_in, const int* in_sizes, int n_in,
                              void* d_out, int out_size) {
    const float* Q = (const float*)d_in[0];
    const float* K = (const float*)d_in[1];
    const float* V = (const float*)d_in[2];
    const float* G = (const float*)d_in[3];
    const float* B = (const float*)d_in[4];
    float* O = (float*)d_out;

    k_sums<<<dim3(CH1, NB), 128>>>(Q, K);
    r_sums2<<<32, 1024>>>();
    k_norm<<<dim3(CH2, NB), 256>>>();
    r_norm2<<<32, 1024>>>();
    k_kv<<<dim3(CH4, HH, NB), 256>>>(V);
    r_kv<<<NHTOT, 256>>>();
    k_out<<<dim3(CH5, NB), 128>>>(V, G, B, O);
}

// round 13
// speedup vs baseline: 1.2486x; 1.2486x over previous
#include <cuda_runtime.h>
#include <cuda_fp16.h>

// Flow attention, N=4, L=S=16384, H=8, D=16, fp32, layout [N, L, H, D].
#define NB 4
#define LL 16384
#define HH 8
#define DD 16
#define HD 128          // H*D floats per (n,l) row
#define NHTOT 32
#define EPSF 1e-6f
#define LN_EPSF 1e-5f

#define CH1 256
#define ROWS1 (LL / CH1)      // 64
#define CH2 256
#define ROWS2 (LL / CH2)      // 64
#define CH4 64
#define ROWS4 (LL / CH4)      // 256
#define TILES4 (ROWS4 / 32)   // 8
#define CH5 256
#define ROWS5 (LL / CH5)      // 64

// ---- scratch (device globals: allowed) ----
__device__ __half g_qs[(size_t)NB * LL * HD];   // sigm(Q), fp16
__device__ __half g_ks[(size_t)NB * LL * HD];   // sigm(K), fp16
__device__ float g_p_qsum[NB][CH1][HD];
__device__ float g_p_ksum[NB][CH1][HD];
__device__ float g_qsum[NB][HD];
__device__ float g_ksum[NB][HD];
__device__ float g_p_qn[NB][CH2][HD];
__device__ float g_p_kn[NB][CH2][HD];
__device__ float g_qn[NB][HD];
__device__ float g_kn[NB][HD];
__device__ float g_p_s[NHTOT][CH4];        // per-chunk sum exp(cr)
__device__ float g_p_kv[NHTOT][CH4][256];  // unnormalized kv partials
__device__ float g_kv[NHTOT][256];

// sigmoid via MUFU.TANH: sigm(x) = 0.5*tanh(x/2)+0.5  (1 MUFU)
__device__ __forceinline__ float sigm(float x) {
    float t;
    asm("tanh.approx.f32 %0, %1;" : "=f"(t) : "f"(x * 0.5f));
    return fmaf(0.5f, t, 0.5f);
}
// 8-lane segment sum via shuffle butterfly; all lanes get the result
__device__ __forceinline__ float red8(float v) {
    v += __shfl_xor_sync(0xffffffffu, v, 4, 8);
    v += __shfl_xor_sync(0xffffffffu, v, 2, 8);
    v += __shfl_xor_sync(0xffffffffu, v, 1, 8);
    return v;
}
__device__ __forceinline__ float red32(float v) {
    v += __shfl_xor_sync(0xffffffffu, v, 16);
    v += __shfl_xor_sync(0xffffffffu, v, 8);
    v += __shfl_xor_sync(0xffffffffu, v, 4);
    v += __shfl_xor_sync(0xffffffffu, v, 2);
    v += __shfl_xor_sync(0xffffffffu, v, 1);
    return v;
}
// packed f32x2 helpers (sm_100+ PTX)
__device__ __forceinline__ unsigned long long pk2(float a, float b) {
    unsigned long long r;
    asm("mov.b64 %0, {%1, %2};" : "=l"(r)
        : "r"(__float_as_uint(a)), "r"(__float_as_uint(b)));
    return r;
}
__device__ __forceinline__ float2 upk2(unsigned long long v) {
    unsigned lo, hi;
    asm("mov.b64 {%0, %1}, %2;" : "=r"(lo), "=r"(hi) : "l"(v));
    return make_float2(__uint_as_float(lo), __uint_as_float(hi));
}
__device__ __forceinline__ unsigned long long fma2(unsigned long long a,
                                                  unsigned long long b,
                                                  unsigned long long c) {
    unsigned long long r;
    asm("fma.rn.f32x2 %0, %1, %2, %3;" : "=l"(r) : "l"(a), "l"(b), "l"(c));
    return r;
}

// ---------- Pass 1: sigmoid + fp16 scratch + per-chunk sums ----------
__global__ __launch_bounds__(128) void k_sums(const float* __restrict__ Q,
                                              const float* __restrict__ K) {
    int c = blockIdx.x, n = blockIdx.y, t = threadIdx.x;
    size_t base = ((size_t)n * LL + (size_t)c * ROWS1) * HD + t;
    float sq = 0.f, sk = 0.f;
#pragma unroll 4
    for (int i = 0; i < ROWS1; i++) {
        size_t off = base + (size_t)i * HD;
        float qs = sigm(Q[off]);
        float ks = sigm(K[off]);
        g_qs[off] = __float2half_rn(qs);
        g_ks[off] = __float2half_rn(ks);
        sq += qs; sk += ks;
    }
    g_p_qsum[n][c][t] = sq;
    g_p_ksum[n][c][t] = sk;
}

// fixup, grid=32: b -> a=b&1, n=(b>>1)&3, tq=b>>3; block 1024 = 32t x 32s
__global__ __launch_bounds__(1024) void r_sums2() {
    __shared__ float red[32][33];
    int b = blockIdx.x;
    int a = b & 1, n = (b >> 1) & 3, tq = b >> 3;
    int lane = threadIdx.x & 31;
    int s = threadIdx.x >> 5;
    int t = tq * 32 + lane;
    float acc = 0.f;
#pragma unroll
    for (int j = 0; j < CH1 / 32; j++) {
        int c = s * (CH1 / 32) + j;
        acc += a ? g_p_ksum[n][c][t] : g_p_qsum[n][c][t];
    }
    red[s][lane] = acc;
    __syncthreads();
    if (threadIdx.x < 32) {
        float r = 0.f;
#pragma unroll
        for (int j = 0; j < 32; j++) r += red[j][threadIdx.x];
        int tt = tq * 32 + (int)threadIdx.x;
        if (a) g_ksum[n][tt] = r; else g_qsum[n][tt] = r;
    }
}

// ---------- Pass 2: qn = sum q*nr, kn = sum k*nc (fp16 reads) ----------
__global__ __launch_bounds__(256) void k_norm() {
    __shared__ float smq[8][HD];
    __shared__ float smk[8][HD];
    int c = blockIdx.x, n = blockIdx.y;
    int t = threadIdx.x, w = t >> 5, lane = t & 31;
    int g = lane >> 3, dp = lane & 7;
    int ta = g * 16 + 2 * dp, tb = (g + 4) * 16 + 2 * dp;
    float2 kseA = {g_ksum[n][ta] + EPSF, g_ksum[n][ta + 1] + EPSF};
    float2 kseB = {g_ksum[n][tb] + EPSF, g_ksum[n][tb + 1] + EPSF};
    float2 qseA = {g_qsum[n][ta] + EPSF, g_qsum[n][ta + 1] + EPSF};
    float2 qseB = {g_qsum[n][tb] + EPSF, g_qsum[n][tb + 1] + EPSF};
    float CkA = red8(kseA.x + kseA.y) * EPSF;
    float CkB = red8(kseB.x + kseB.y) * EPSF;
    float CqA = red8(qseA.x + qseA.y) * EPSF;
    float CqB = red8(qseB.x + qseB.y) * EPSF;
    float2 aqA = {0.f, 0.f}, aqB = {0.f, 0.f};
    float2 akA = {0.f, 0.f}, akB = {0.f, 0.f};
    size_t rb0 = ((size_t)n * LL + (size_t)c * ROWS2) * HD;
#pragma unroll 2
    for (int i = 0; i < ROWS2 / 8; i++) {
        size_t rb = rb0 + (size_t)(w + 8 * i) * HD;
        float2 qa = __half22float2(*(const __half2*)(g_qs + rb + ta));
        float2 qb = __half22float2(*(const __half2*)(g_qs + rb + tb));
        float2 ka = __half22float2(*(const __half2*)(g_ks + rb + ta));
        float2 kb = __half22float2(*(const __half2*)(g_ks + rb + tb));
        float d1A = red8(fmaf(qa.y, kseA.y, qa.x * kseA.x)) + CkA;
        float d1B = red8(fmaf(qb.y, kseB.y, qb.x * kseB.x)) + CkB;
        float d2A = red8(fmaf(ka.y, qseA.y, ka.x * qseA.x)) + CqA;
        float d2B = red8(fmaf(kb.y, qseB.y, kb.x * qseB.x)) + CqB;
        float nrA = __fdividef(1.f, d1A), nrB = __fdividef(1.f, d1B);
        float ncA = __fdividef(1.f, d2A), ncB = __fdividef(1.f, d2B);
        aqA.x = fmaf(qa.x, nrA, aqA.x); aqA.y = fmaf(qa.y, nrA, aqA.y);
        aqB.x = fmaf(qb.x, nrB, aqB.x); aqB.y = fmaf(qb.y, nrB, aqB.y);
        akA.x = fmaf(ka.x, ncA, akA.x); akA.y = fmaf(ka.y, ncA, akA.y);
        akB.x = fmaf(kb.x, ncB, akB.x); akB.y = fmaf(kb.y, ncB, akB.y);
    }
    *(float2*)&smq[w][ta] = aqA; *(float2*)&smq[w][tb] = aqB;
    *(float2*)&smk[w][ta] = akA; *(float2*)&smk[w][tb] = akB;
    __syncthreads();
    if (t < 128) {
        float s = 0.f;
#pragma unroll
        for (int w2 = 0; w2 < 8; w2++) s += smq[w2][t];
        g_p_qn[n][c][t] = s;
    } else {
        int t2 = t - 128;
        float s = 0.f;
#pragma unroll
        for (int w2 = 0; w2 < 8; w2++) s += smk[w2][t2];
        g_p_kn[n][c][t2] = s;
    }
}

__global__ __launch_bounds__(1024) void r_norm2() {
    __shared__ float red[32][33];
    int b = blockIdx.x;
    int a = b & 1, n = (b >> 1) & 3, tq = b >> 3;
    int lane = threadIdx.x & 31;
    int s = threadIdx.x >> 5;
    int t = tq * 32 + lane;
    float acc = 0.f;
#pragma unroll
    for (int j = 0; j < CH2 / 32; j++) {
        int c = s * (CH2 / 32) + j;
        acc += a ? g_p_kn[n][c][t] : g_p_qn[n][c][t];
    }
    red[s][lane] = acc;
    __syncthreads();
    if (threadIdx.x < 32) {
        float r = 0.f;
#pragma unroll
        for (int j = 0; j < 32; j++) r += red[j][threadIdx.x];
        int tt = tq * 32 + (int)threadIdx.x;
        if (a) g_kn[n][tt] = r; else g_qn[n][tt] = r;
    }
}

// ---------- Pass 3: kv accumulation, shift-free softmax weights ----------
__global__ __launch_bounds__(256) void k_kv(const float* __restrict__ V) {
    __shared__ __align__(16) float k_sh[2][32][16];
    __shared__ __align__(16) float v_sh[2][32][16];
    __shared__ float w_sh[2][32];
    __shared__ float s_sh[32];
    __shared__ float red_sh[8][16][16];
    int c = blockIdx.x, h = blockIdx.y, n = blockIdx.z;
    int t = threadIdx.x;  // 256
    int nh = n * HH + h;
    int lrow = t >> 3, ldp = t & 7;
    float2 qne = {g_qn[n][h * 16 + 2 * ldp] + EPSF,
                  g_qn[n][h * 16 + 2 * ldp + 1] + EPSF};
    float Ccr = red8(qne.x + qne.y) * EPSF;
    int pos = t & 15, sl = t >> 4;
    int d4 = (pos & 3) * 4, e4 = (pos >> 2) * 4;
    float acc[16];
#pragma unroll
    for (int i = 0; i < 16; i++) acc[i] = 0.f;
    float s_acc = 0.f;   // valid on ldp==0 threads
    size_t base = ((size_t)n * LL + (size_t)c * ROWS4) * HD + h * DD;
    // prologue: load tile 0 into buffer 0
    {
        size_t off = base + (size_t)lrow * HD + 2 * ldp;
        float2 kf = __half22float2(*(const __half2*)(g_ks + off));
        float2 vf = *(const float2*)(V + off);
        *(float2*)&k_sh[0][lrow][2 * ldp] = kf;
        *(float2*)&v_sh[0][lrow][2 * ldp] = vf;
        float cr = red8(fmaf(kf.y, qne.y, kf.x * qne.x)) + Ccr;
        if (ldp == 0) { float w = __expf(cr); w_sh[0][lrow] = w; s_acc += w; }
    }
    for (int tile = 0; tile < TILES4; tile++) {
        int p = tile & 1;
        __syncthreads();   // buffer p fully written; buffer 1-p free
        if (tile + 1 < TILES4) {
            size_t off = base + (size_t)((tile + 1) * 32 + lrow) * HD + 2 * ldp;
            float2 kf = __half22float2(*(const __half2*)(g_ks + off));
            float2 vf = *(const float2*)(V + off);
            *(float2*)&k_sh[1 - p][lrow][2 * ldp] = kf;
            *(float2*)&v_sh[1 - p][lrow][2 * ldp] = vf;
            float cr = red8(fmaf(kf.y, qne.y, kf.x * qne.x)) + Ccr;
            if (ldp == 0) { float w = __expf(cr); w_sh[1 - p][lrow] = w; s_acc += w; }
        }
        // 4x4 register-tiled rank-1 accumulation from buffer p
#pragma unroll
        for (int j = 0; j < 2; j++) {
            int ss = sl + j * 16;
            float c0 = w_sh[p][ss];
            float4 kq = *reinterpret_cast<const float4*>(&k_sh[p][ss][d4]);
            float4 vq = *reinterpret_cast<const float4*>(&v_sh[p][ss][e4]);
            float ka[4] = {kq.x * c0, kq.y * c0, kq.z * c0, kq.w * c0};
            float va[4] = {vq.x, vq.y, vq.z, vq.w};
#pragma unroll
            for (int di = 0; di < 4; di++)
#pragma unroll
                for (int ei = 0; ei < 4; ei++)
                    acc[di * 4 + ei] = fmaf(ka[di], va[ei], acc[di * 4 + ei]);
        }
    }
    if (ldp == 0) s_sh[lrow] = s_acc;
#pragma unroll
    for (int i = 0; i < 16; i++) acc[i] += __shfl_xor_sync(0xffffffffu, acc[i], 16);
    int w = t >> 5, lane = t & 31;
    __syncthreads();
    if (t < 32) {
        float z = red32(s_sh[t]);
        if (t == 0) g_p_s[nh][c] = z;
    }
    if (lane < 16) {
#pragma unroll
        for (int i = 0; i < 16; i++) red_sh[w][lane][i] = acc[i];
    }
    __syncthreads();
    {
        int posp = t >> 4, ip = t & 15;
        float s = 0.f;
#pragma unroll
        for (int w2 = 0; w2 < 8; w2++) s += red_sh[w2][posp][ip];
        int dd4 = (posp & 3) * 4, ee4 = (posp >> 2) * 4;
        int di = ip >> 2, ei = ip & 3;
        g_p_kv[nh][c][(dd4 + di) * 16 + (ee4 + ei)] = s;
    }
}

// combine chunk kv partials, normalize by Z, fold in S factor
__global__ __launch_bounds__(256) void r_kv() {
    __shared__ float sf[CH4];
    __shared__ float scale_sh;
    int nh = blockIdx.x, t = threadIdx.x;
    if (t < CH4) sf[t] = g_p_s[nh][t];
    __syncthreads();
    if (t == 0) {
        float Z = 0.f;
        for (int c = 0; c < CH4; c++) Z += sf[c];
        scale_sh = (float)LL / Z;
    }
    __syncthreads();
    float scale = scale_sh;
    float s = 0.f;
#pragma unroll 8
    for (int c = 0; c < CH4; c++) s += g_p_kv[nh][c][t];
    g_kv[nh][t] = s * scale;
}

// ---------- Pass 5: out = LN(v + (q @ kv) * nr * rr) ----------
__global__ __launch_bounds__(128) void k_out(const float* __restrict__ V,
                                             const float* __restrict__ G,
                                             const float* __restrict__ B,
                                             float* __restrict__ O) {
    int c = blockIdx.x, n = blockIdx.y, t = threadIdx.x;  // 128
    int rh = t >> 6;          // which of 2 rows per iter
    int h = (t >> 3) & 7;
    int ep = t & 7;           // e = 2ep, 2ep+1
    int nh = n * HH + h;
    int tb = h * 16 + 2 * ep;
    float2 kse2 = {g_ksum[n][tb] + EPSF, g_ksum[n][tb + 1] + EPSF};
    float2 kne2 = {g_kn[n][tb] + EPSF, g_kn[n][tb + 1] + EPSF};
    float Ck = red8(kse2.x + kse2.y) * EPSF;
    float Cn = red8(kne2.x + kne2.y) * EPSF;
    float2 gam = {G[2 * ep], G[2 * ep + 1]};
    float2 bet = {B[2 * ep], B[2 * ep + 1]};
    unsigned long long kvp[16];
#pragma unroll
    for (int d = 0; d < 16; d++)
        kvp[d] = pk2(g_kv[nh][d * 16 + 2 * ep], g_kv[nh][d * 16 + 2 * ep + 1]);
    for (int i = 0; i < ROWS5 / 2; i++) {
        int l = c * ROWS5 + 2 * i + rh;
        size_t rowb = ((size_t)n * LL + (size_t)l) * HD;
        const __half* qh = g_qs + rowb + h * 16;
        uint4 a0 = *(const uint4*)qh;
        uint4 a1 = *(const uint4*)(qh + 8);
        float2 q01 = __half22float2(*(const __half2*)&a0.x);
        float2 q23 = __half22float2(*(const __half2*)&a0.y);
        float2 q45 = __half22float2(*(const __half2*)&a0.z);
        float2 q67 = __half22float2(*(const __half2*)&a0.w);
        float2 q89 = __half22float2(*(const __half2*)&a1.x);
        float2 qab = __half22float2(*(const __half2*)&a1.y);
        float2 qcd = __half22float2(*(const __half2*)&a1.z);
        float2 qef = __half22float2(*(const __half2*)&a1.w);
        float qv[16] = {q01.x, q01.y, q23.x, q23.y, q45.x, q45.y, q67.x, q67.y,
                        q89.x, q89.y, qab.x, qab.y, qcd.x, qcd.y, qef.x, qef.y};
        unsigned long long acc = pk2(0.f, 0.f);
#pragma unroll
        for (int d = 0; d < 16; d++)
            acc = fma2(pk2(qv[d], qv[d]), kvp[d], acc);
        float2 x = upk2(acc);
        float2 qs2 = __half22float2(*(const __half2*)(qh + 2 * ep));
        float d1 = red8(fmaf(qs2.y, kse2.y, qs2.x * kse2.x)) + Ck;
        float d2 = red8(fmaf(qs2.y, kne2.y, qs2.x * kne2.x)) + Cn;
        float s = __fdividef(1.f, d1) * sigm(d2);
        float2 v2 = *(const float2*)(V + rowb + tb);
        float y0 = fmaf(x.x, s, v2.x);
        float y1 = fmaf(x.y, s, v2.y);
        float mean = red8(y0 + y1) * 0.0625f;
        float ym0 = y0 - mean, ym1 = y1 - mean;
        float var = red8(fmaf(ym1, ym1, ym0 * ym0)) * 0.0625f;
        float rs = rsqrtf(var + LN_EPSF);
        float2 o;
        o.x = fmaf(ym0 * rs, gam.x, bet.x);
        o.y = fmaf(ym1 * rs, gam.y, bet.y);
        *(float2*)(O + rowb + tb) = o;
    }
}

extern "C" void kernel_launch(void* const* d_in, const int* in_sizes, int n_in,
                              void* d_out, int out_size) {
    const float* Q = (const float*)d_in[0];
    const float* K = (const float*)d_in[1];
    const float* V = (const float*)d_in[2];
    const float* G = (const float*)d_in[3];
    const float* B = (const float*)d_in[4];
    float* O = (float*)d_out;

    k_sums<<<dim3(CH1, NB), 128>>>(Q, K);
    r_sums2<<<32, 1024>>>();
    k_norm<<<dim3(CH2, NB), 256>>>();
    r_norm2<<<32, 1024>>>();
    k_kv<<<dim3(CH4, HH, NB), 256>>>(V);
    r_kv<<<NHTOT, 256>>>();
    k_out<<<dim3(CH5, NB), 128>>>(V, G, B, O);
}

// round 14
// speedup vs baseline: 1.2512x; 1.0021x over previous
#include <cuda_runtime.h>
#include <cuda_fp16.h>

// Flow attention, N=4, L=S=16384, H=8, D=16, fp32, layout [N, L, H, D].
#define NB 4
#define LL 16384
#define HH 8
#define DD 16
#define HD 128          // H*D floats per (n,l) row
#define NHTOT 32
#define EPSF 1e-6f
#define LN_EPSF 1e-5f

#define CH1 256
#define ROWS1 (LL / CH1)      // 64
#define CH1P (CH1 * 4)        // 1024 partial slots (4 row-phases per chunk)
#define CH2 256
#define ROWS2 (LL / CH2)      // 64
#define CH4 64
#define ROWS4 (LL / CH4)      // 256
#define TILES4 (ROWS4 / 32)   // 8
#define CH5 256
#define ROWS5 (LL / CH5)      // 64

// ---- scratch (device globals: allowed) ----
__device__ __half g_qs[(size_t)NB * LL * HD];   // sigm(Q), fp16
__device__ __half g_ks[(size_t)NB * LL * HD];   // sigm(K), fp16
__device__ float g_p_qsum[NB][CH1P][HD];
__device__ float g_p_ksum[NB][CH1P][HD];
__device__ float g_qsum[NB][HD];
__device__ float g_ksum[NB][HD];
__device__ float g_p_qn[NB][CH2][HD];
__device__ float g_p_kn[NB][CH2][HD];
__device__ float g_qn[NB][HD];
__device__ float g_kn[NB][HD];
__device__ float g_p_s[NHTOT][CH4];        // per-chunk sum exp(cr)
__device__ float g_p_kv[NHTOT][CH4][256];  // unnormalized kv partials
__device__ float g_kv[NHTOT][256];

// sigmoid via MUFU.TANH: sigm(x) = 0.5*tanh(x/2)+0.5  (1 MUFU)
__device__ __forceinline__ float sigm(float x) {
    float t;
    asm("tanh.approx.f32 %0, %1;" : "=f"(t) : "f"(x * 0.5f));
    return fmaf(0.5f, t, 0.5f);
}
// 8-lane segment sum via shuffle butterfly; all lanes get the result
__device__ __forceinline__ float red8(float v) {
    v += __shfl_xor_sync(0xffffffffu, v, 4, 8);
    v += __shfl_xor_sync(0xffffffffu, v, 2, 8);
    v += __shfl_xor_sync(0xffffffffu, v, 1, 8);
    return v;
}
__device__ __forceinline__ float red32(float v) {
    v += __shfl_xor_sync(0xffffffffu, v, 16);
    v += __shfl_xor_sync(0xffffffffu, v, 8);
    v += __shfl_xor_sync(0xffffffffu, v, 4);
    v += __shfl_xor_sync(0xffffffffu, v, 2);
    v += __shfl_xor_sync(0xffffffffu, v, 1);
    return v;
}
// packed f32x2 helpers (sm_100+ PTX)
__device__ __forceinline__ unsigned long long pk2(float a, float b) {
    unsigned long long r;
    asm("mov.b64 %0, {%1, %2};" : "=l"(r)
        : "r"(__float_as_uint(a)), "r"(__float_as_uint(b)));
    return r;
}
__device__ __forceinline__ float2 upk2(unsigned long long v) {
    unsigned lo, hi;
    asm("mov.b64 {%0, %1}, %2;" : "=r"(lo), "=r"(hi) : "l"(v));
    return make_float2(__uint_as_float(lo), __uint_as_float(hi));
}
__device__ __forceinline__ unsigned long long fma2(unsigned long long a,
                                                  unsigned long long b,
                                                  unsigned long long c) {
    unsigned long long r;
    asm("fma.rn.f32x2 %0, %1, %2, %3;" : "=l"(r) : "l"(a), "l"(b), "l"(c));
    return r;
}

// ---------- Pass 1: sigmoid + fp16 scratch + per-chunk sums ----------
// thread: u = t&31 covers columns 4u..4u+3; r = t>>5 covers rows 4i+r.
// float4 loads (16 B/lane), half4 stores (8 B/lane). Partial slot = 4c+r.
__global__ __launch_bounds__(128) void k_sums(const float* __restrict__ Q,
                                              const float* __restrict__ K) {
    int c = blockIdx.x, n = blockIdx.y, t = threadIdx.x;
    int u = t & 31, r = t >> 5;
    size_t base = ((size_t)n * LL + (size_t)c * ROWS1 + r) * HD + 4 * u;
    float4 sq = {0.f, 0.f, 0.f, 0.f}, sk = {0.f, 0.f, 0.f, 0.f};
#pragma unroll 4
    for (int i = 0; i < ROWS1 / 4; i++) {
        size_t off = base + (size_t)i * 4 * HD;
        float4 q4 = *(const float4*)(Q + off);
        float4 k4 = *(const float4*)(K + off);
        float q0 = sigm(q4.x), q1 = sigm(q4.y), q2 = sigm(q4.z), q3 = sigm(q4.w);
        float k0 = sigm(k4.x), k1 = sigm(k4.y), k2 = sigm(k4.z), k3 = sigm(k4.w);
        __half2 qh01 = __floats2half2_rn(q0, q1);
        __half2 qh23 = __floats2half2_rn(q2, q3);
        __half2 kh01 = __floats2half2_rn(k0, k1);
        __half2 kh23 = __floats2half2_rn(k2, k3);
        uint2 qp, kp;
        qp.x = *(unsigned*)&qh01; qp.y = *(unsigned*)&qh23;
        kp.x = *(unsigned*)&kh01; kp.y = *(unsigned*)&kh23;
        *(uint2*)(g_qs + off) = qp;
        *(uint2*)(g_ks + off) = kp;
        sq.x += q0; sq.y += q1; sq.z += q2; sq.w += q3;
        sk.x += k0; sk.y += k1; sk.z += k2; sk.w += k3;
    }
    *(float4*)&g_p_qsum[n][c * 4 + r][4 * u] = sq;
    *(float4*)&g_p_ksum[n][c * 4 + r][4 * u] = sk;
}

// fixup, grid=32: b -> a=b&1, n=(b>>1)&3, tq=b>>3; block 1024 = 32t x 32s
__global__ __launch_bounds__(1024) void r_sums2() {
    __shared__ float red[32][33];
    int b = blockIdx.x;
    int a = b & 1, n = (b >> 1) & 3, tq = b >> 3;
    int lane = threadIdx.x & 31;
    int s = threadIdx.x >> 5;
    int t = tq * 32 + lane;
    float acc = 0.f;
#pragma unroll
    for (int j = 0; j < CH1P / 32; j++) {
        int c = s * (CH1P / 32) + j;
        acc += a ? g_p_ksum[n][c][t] : g_p_qsum[n][c][t];
    }
    red[s][lane] = acc;
    __syncthreads();
    if (threadIdx.x < 32) {
        float r = 0.f;
#pragma unroll
        for (int j = 0; j < 32; j++) r += red[j][threadIdx.x];
        int tt = tq * 32 + (int)threadIdx.x;
        if (a) g_ksum[n][tt] = r; else g_qsum[n][tt] = r;
    }
}

// ---------- Pass 2: qn = sum q*nr, kn = sum k*nc (fp16 reads) ----------
__global__ __launch_bounds__(256) void k_norm() {
    __shared__ float smq[8][HD];
    __shared__ float smk[8][HD];
    int c = blockIdx.x, n = blockIdx.y;
    int t = threadIdx.x, w = t >> 5, lane = t & 31;
    int g = lane >> 3, dp = lane & 7;
    int ta = g * 16 + 2 * dp, tb = (g + 4) * 16 + 2 * dp;
    float2 kseA = {g_ksum[n][ta] + EPSF, g_ksum[n][ta + 1] + EPSF};
    float2 kseB = {g_ksum[n][tb] + EPSF, g_ksum[n][tb + 1] + EPSF};
    float2 qseA = {g_qsum[n][ta] + EPSF, g_qsum[n][ta + 1] + EPSF};
    float2 qseB = {g_qsum[n][tb] + EPSF, g_qsum[n][tb + 1] + EPSF};
    float CkA = red8(kseA.x + kseA.y) * EPSF;
    float CkB = red8(kseB.x + kseB.y) * EPSF;
    float CqA = red8(qseA.x + qseA.y) * EPSF;
    float CqB = red8(qseB.x + qseB.y) * EPSF;
    float2 aqA = {0.f, 0.f}, aqB = {0.f, 0.f};
    float2 akA = {0.f, 0.f}, akB = {0.f, 0.f};
    size_t rb0 = ((size_t)n * LL + (size_t)c * ROWS2) * HD;
#pragma unroll 2
    for (int i = 0; i < ROWS2 / 8; i++) {
        size_t rb = rb0 + (size_t)(w + 8 * i) * HD;
        float2 qa = __half22float2(*(const __half2*)(g_qs + rb + ta));
        float2 qb = __half22float2(*(const __half2*)(g_qs + rb + tb));
        float2 ka = __half22float2(*(const __half2*)(g_ks + rb + ta));
        float2 kb = __half22float2(*(const __half2*)(g_ks + rb + tb));
        float d1A = red8(fmaf(qa.y, kseA.y, qa.x * kseA.x)) + CkA;
        float d1B = red8(fmaf(qb.y, kseB.y, qb.x * kseB.x)) + CkB;
        float d2A = red8(fmaf(ka.y, qseA.y, ka.x * qseA.x)) + CqA;
        float d2B = red8(fmaf(kb.y, qseB.y, kb.x * qseB.x)) + CqB;
        float nrA = __fdividef(1.f, d1A), nrB = __fdividef(1.f, d1B);
        float ncA = __fdividef(1.f, d2A), ncB = __fdividef(1.f, d2B);
        aqA.x = fmaf(qa.x, nrA, aqA.x); aqA.y = fmaf(qa.y, nrA, aqA.y);
        aqB.x = fmaf(qb.x, nrB, aqB.x); aqB.y = fmaf(qb.y, nrB, aqB.y);
        akA.x = fmaf(ka.x, ncA, akA.x); akA.y = fmaf(ka.y, ncA, akA.y);
        akB.x = fmaf(kb.x, ncB, akB.x); akB.y = fmaf(kb.y, ncB, akB.y);
    }
    *(float2*)&smq[w][ta] = aqA; *(float2*)&smq[w][tb] = aqB;
    *(float2*)&smk[w][ta] = akA; *(float2*)&smk[w][tb] = akB;
    __syncthreads();
    if (t < 128) {
        float s = 0.f;
#pragma unroll
        for (int w2 = 0; w2 < 8; w2++) s += smq[w2][t];
        g_p_qn[n][c][t] = s;
    } else {
        int t2 = t - 128;
        float s = 0.f;
#pragma unroll
        for (int w2 = 0; w2 < 8; w2++) s += smk[w2][t2];
        g_p_kn[n][c][t2] = s;
    }
}

__global__ __launch_bounds__(1024) void r_norm2() {
    __shared__ float red[32][33];
    int b = blockIdx.x;
    int a = b & 1, n = (b >> 1) & 3, tq = b >> 3;
    int lane = threadIdx.x & 31;
    int s = threadIdx.x >> 5;
    int t = tq * 32 + lane;
    float acc = 0.f;
#pragma unroll
    for (int j = 0; j < CH2 / 32; j++) {
        int c = s * (CH2 / 32) + j;
        acc += a ? g_p_kn[n][c][t] : g_p_qn[n][c][t];
    }
    red[s][lane] = acc;
    __syncthreads();
    if (threadIdx.x < 32) {
        float r = 0.f;
#pragma unroll
        for (int j = 0; j < 32; j++) r += red[j][threadIdx.x];
        int tt = tq * 32 + (int)threadIdx.x;
        if (a) g_kn[n][tt] = r; else g_qn[n][tt] = r;
    }
}

// ---------- Pass 3: kv accumulation, shift-free softmax weights ----------
__global__ __launch_bounds__(256) void k_kv(const float* __restrict__ V) {
    __shared__ __align__(16) float k_sh[2][32][16];
    __shared__ __align__(16) float v_sh[2][32][16];
    __shared__ float w_sh[2][32];
    __shared__ float s_sh[32];
    __shared__ float red_sh[8][16][16];
    int c = blockIdx.x, h = blockIdx.y, n = blockIdx.z;
    int t = threadIdx.x;  // 256
    int nh = n * HH + h;
    int lrow = t >> 3, ldp = t & 7;
    float2 qne = {g_qn[n][h * 16 + 2 * ldp] + EPSF,
                  g_qn[n][h * 16 + 2 * ldp + 1] + EPSF};
    float Ccr = red8(qne.x + qne.y) * EPSF;
    int pos = t & 15, sl = t >> 4;
    int d4 = (pos & 3) * 4, e4 = (pos >> 2) * 4;
    float acc[16];
#pragma unroll
    for (int i = 0; i < 16; i++) acc[i] = 0.f;
    float s_acc = 0.f;   // valid on ldp==0 threads
    size_t base = ((size_t)n * LL + (size_t)c * ROWS4) * HD + h * DD;
    // prologue: load tile 0 into buffer 0
    {
        size_t off = base + (size_t)lrow * HD + 2 * ldp;
        float2 kf = __half22float2(*(const __half2*)(g_ks + off));
        float2 vf = *(const float2*)(V + off);
        *(float2*)&k_sh[0][lrow][2 * ldp] = kf;
        *(float2*)&v_sh[0][lrow][2 * ldp] = vf;
        float cr = red8(fmaf(kf.y, qne.y, kf.x * qne.x)) + Ccr;
        if (ldp == 0) { float w = __expf(cr); w_sh[0][lrow] = w; s_acc += w; }
    }
    for (int tile = 0; tile < TILES4; tile++) {
        int p = tile & 1;
        __syncthreads();   // buffer p fully written; buffer 1-p free
        if (tile + 1 < TILES4) {
            size_t off = base + (size_t)((tile + 1) * 32 + lrow) * HD + 2 * ldp;
            float2 kf = __half22float2(*(const __half2*)(g_ks + off));
            float2 vf = *(const float2*)(V + off);
            *(float2*)&k_sh[1 - p][lrow][2 * ldp] = kf;
            *(float2*)&v_sh[1 - p][lrow][2 * ldp] = vf;
            float cr = red8(fmaf(kf.y, qne.y, kf.x * qne.x)) + Ccr;
            if (ldp == 0) { float w = __expf(cr); w_sh[1 - p][lrow] = w; s_acc += w; }
        }
        // 4x4 register-tiled rank-1 accumulation from buffer p
#pragma unroll
        for (int j = 0; j < 2; j++) {
            int ss = sl + j * 16;
            float c0 = w_sh[p][ss];
            float4 kq = *reinterpret_cast<const float4*>(&k_sh[p][ss][d4]);
            float4 vq = *reinterpret_cast<const float4*>(&v_sh[p][ss][e4]);
            float ka[4] = {kq.x * c0, kq.y * c0, kq.z * c0, kq.w * c0};
            float va[4] = {vq.x, vq.y, vq.z, vq.w};
#pragma unroll
            for (int di = 0; di < 4; di++)
#pragma unroll
                for (int ei = 0; ei < 4; ei++)
                    acc[di * 4 + ei] = fmaf(ka[di], va[ei], acc[di * 4 + ei]);
        }
    }
    if (ldp == 0) s_sh[lrow] = s_acc;
#pragma unroll
    for (int i = 0; i < 16; i++) acc[i] += __shfl_xor_sync(0xffffffffu, acc[i], 16);
    int w = t >> 5, lane = t & 31;
    __syncthreads();
    if (t < 32) {
        float z = red32(s_sh[t]);
        if (t == 0) g_p_s[nh][c] = z;
    }
    if (lane < 16) {
#pragma unroll
        for (int i = 0; i < 16; i++) red_sh[w][lane][i] = acc[i];
    }
    __syncthreads();
    {
        int posp = t >> 4, ip = t & 15;
        float s = 0.f;
#pragma unroll
        for (int w2 = 0; w2 < 8; w2++) s += red_sh[w2][posp][ip];
        int dd4 = (posp & 3) * 4, ee4 = (posp >> 2) * 4;
        int di = ip >> 2, ei = ip & 3;
        g_p_kv[nh][c][(dd4 + di) * 16 + (ee4 + ei)] = s;
    }
}

// combine chunk kv partials, normalize by Z, fold in S factor
__global__ __launch_bounds__(256) void r_kv() {
    __shared__ float sf[CH4];
    __shared__ float scale_sh;
    int nh = blockIdx.x, t = threadIdx.x;
    if (t < CH4) sf[t] = g_p_s[nh][t];
    __syncthreads();
    if (t == 0) {
        float Z = 0.f;
        for (int c = 0; c < CH4; c++) Z += sf[c];
        scale_sh = (float)LL / Z;
    }
    __syncthreads();
    float scale = scale_sh;
    float s = 0.f;
#pragma unroll 8
    for (int c = 0; c < CH4; c++) s += g_p_kv[nh][c][t];
    g_kv[nh][t] = s * scale;
}

// ---------- Pass 5: out = LN(v + (q @ kv) * nr * rr) ----------
__global__ __launch_bounds__(128) void k_out(const float* __restrict__ V,
                                             const float* __restrict__ G,
                                             const float* __restrict__ B,
                                             float* __restrict__ O) {
    int c = blockIdx.x, n = blockIdx.y, t = threadIdx.x;  // 128
    int rh = t >> 6;          // which of 2 rows per iter
    int h = (t >> 3) & 7;
    int ep = t & 7;           // e = 2ep, 2ep+1
    int nh = n * HH + h;
    int tb = h * 16 + 2 * ep;
    float2 kse2 = {g_ksum[n][tb] + EPSF, g_ksum[n][tb + 1] + EPSF};
    float2 kne2 = {g_kn[n][tb] + EPSF, g_kn[n][tb + 1] + EPSF};
    float Ck = red8(kse2.x + kse2.y) * EPSF;
    float Cn = red8(kne2.x + kne2.y) * EPSF;
    float2 gam = {G[2 * ep], G[2 * ep + 1]};
    float2 bet = {B[2 * ep], B[2 * ep + 1]};
    unsigned long long kvp[16];
#pragma unroll
    for (int d = 0; d < 16; d++)
        kvp[d] = pk2(g_kv[nh][d * 16 + 2 * ep], g_kv[nh][d * 16 + 2 * ep + 1]);
    for (int i = 0; i < ROWS5 / 2; i++) {
        int l = c * ROWS5 + 2 * i + rh;
        size_t rowb = ((size_t)n * LL + (size_t)l) * HD;
        const __half* qh = g_qs + rowb + h * 16;
        uint4 a0 = *(const uint4*)qh;
        uint4 a1 = *(const uint4*)(qh + 8);
        float2 q01 = __half22float2(*(const __half2*)&a0.x);
        float2 q23 = __half22float2(*(const __half2*)&a0.y);
        float2 q45 = __half22float2(*(const __half2*)&a0.z);
        float2 q67 = __half22float2(*(const __half2*)&a0.w);
        float2 q89 = __half22float2(*(const __half2*)&a1.x);
        float2 qab = __half22float2(*(const __half2*)&a1.y);
        float2 qcd = __half22float2(*(const __half2*)&a1.z);
        float2 qef = __half22float2(*(const __half2*)&a1.w);
        float qv[16] = {q01.x, q01.y, q23.x, q23.y, q45.x, q45.y, q67.x, q67.y,
                        q89.x, q89.y, qab.x, qab.y, qcd.x, qcd.y, qef.x, qef.y};
        unsigned long long acc = pk2(0.f, 0.f);
#pragma unroll
        for (int d = 0; d < 16; d++)
            acc = fma2(pk2(qv[d], qv[d]), kvp[d], acc);
        float2 x = upk2(acc);
        float2 qs2 = __half22float2(*(const __half2*)(qh + 2 * ep));
        float d1 = red8(fmaf(qs2.y, kse2.y, qs2.x * kse2.x)) + Ck;
        float d2 = red8(fmaf(qs2.y, kne2.y, qs2.x * kne2.x)) + Cn;
        float s = __fdividef(1.f, d1) * sigm(d2);
        float2 v2 = *(const float2*)(V + rowb + tb);
        float y0 = fmaf(x.x, s, v2.x);
        float y1 = fmaf(x.y, s, v2.y);
        float mean = red8(y0 + y1) * 0.0625f;
        float ym0 = y0 - mean, ym1 = y1 - mean;
        float var = red8(fmaf(ym1, ym1, ym0 * ym0)) * 0.0625f;
        float rs = rsqrtf(var + LN_EPSF);
        float2 o;
        o.x = fmaf(ym0 * rs, gam.x, bet.x);
        o.y = fmaf(ym1 * rs, gam.y, bet.y);
        *(float2*)(O + rowb + tb) = o;
    }
}

extern "C" void kernel_launch(void* const* d_in, const int* in_sizes, int n_in,
                              void* d_out, int out_size) {
    const float* Q = (const float*)d_in[0];
    const float* K = (const float*)d_in[1];
    const float* V = (const float*)d_in[2];
    const float* G = (const float*)d_in[3];
    const float* B = (const float*)d_in[4];
    float* O = (float*)d_out;

    k_sums<<<dim3(CH1, NB), 128>>>(Q, K);
    r_sums2<<<32, 1024>>>();
    k_norm<<<dim3(CH2, NB), 256>>>();
    r_norm2<<<32, 1024>>>();
    k_kv<<<dim3(CH4, HH, NB), 256>>>(V);
    r_kv<<<NHTOT, 256>>>();
    k_out<<<dim3(CH5, NB), 128>>>(V, G, B, O);
}